// round 3
// baseline (speedup 1.0000x reference)
#include <cuda_runtime.h>

#define DD 64
#define HH 128
#define KK1 192
#define NN 20000
#define EE 640000
#define TILE 128
#define KB 16
#define HS_LD 132

// Scratch for scatter-add aggregation (no device mallocs allowed).
__device__ __align__(16) float g_agg[NN * DD];

__global__ void zero_agg_kernel() {
    int i = blockIdx.x * blockDim.x + threadIdx.x;
    const int n4 = NN * DD / 4;
    if (i < n4) ((float4*)g_agg)[i] = make_float4(0.f, 0.f, 0.f, 0.f);
}

constexpr int SMEM_FLOATS = KB * TILE + KB * HH + TILE * HS_LD + KB * DD;
constexpr int SMEM_BYTES  = SMEM_FLOATS * 4 + 2 * TILE * 4;

// Fused 2-layer MLP over gathered rows.
// MODE 0 (edge): A = [x[src] | x[dest] | edge_attr], out=edge_out, scatter-add to g_agg[dest]
// MODE 1 (node): A = [x | g_agg | f],                out=x_out
template <int MODE>
__global__ void __launch_bounds__(256, 2)
mlp_fused_kernel(const float* __restrict__ x,
                 const int* __restrict__ edge_index,   // int32 (JAX x64 disabled)
                 const float* __restrict__ attr_or_f,
                 const float* __restrict__ W1,
                 const float* __restrict__ b1,
                 const float* __restrict__ W2,
                 const float* __restrict__ b2,
                 float* __restrict__ out,
                 int nrows)
{
    extern __shared__ float smem[];
    float* As  = smem;                 // [KB][TILE]
    float* Bs  = As + KB * TILE;       // [KB][HH]
    float* Hs  = Bs + KB * HH;         // [TILE][HS_LD]
    float* B2s = Hs + TILE * HS_LD;    // [KB][DD]
    int*  src_s = (int*)(B2s + KB * DD);
    int*  dst_s = src_s + TILE;

    const int tid = threadIdx.x;
    const int r0  = blockIdx.x * TILE;

    if (MODE == 0 && tid < TILE) {
        int e = r0 + tid;
        int s = edge_index[e];
        int d = edge_index[EE + e];
        // defensive clamp: wrong dtype / bad index becomes a rel_err, not a crash
        src_s[tid] = (s < 0) ? 0 : (s >= NN ? NN - 1 : s);
        dst_s[tid] = (d < 0) ? 0 : (d >= NN ? NN - 1 : d);
    }
    __syncthreads();

    // ---------------- Stage 1: H = relu(A @ W1 + b1), tile 128x128, K=192 ----
    const int ty = tid >> 4, tx = tid & 15;
    const int row0 = ty << 3, col0 = tx << 3;
    const int e_l = tid >> 1;
    const int sub = tid & 1;

    float acc[8][8];
    #pragma unroll
    for (int i = 0; i < 8; i++)
        #pragma unroll
        for (int j = 0; j < 8; j++) acc[i][j] = 0.f;

    #pragma unroll 1
    for (int k0 = 0; k0 < KK1; k0 += KB) {
        // Gather A tile: thread loads 8 consecutive k for one row (2x float4)
        {
            int kg = k0 + sub * 8;
            const float* base;
            if (MODE == 0) {
                if (kg < DD)        base = x + (size_t)src_s[e_l] * DD + kg;
                else if (kg < 2*DD) base = x + (size_t)dst_s[e_l] * DD + (kg - DD);
                else                base = attr_or_f + (size_t)(r0 + e_l) * DD + (kg - 2*DD);
            } else {
                int n = r0 + e_l; if (n >= nrows) n = nrows - 1;
                if (kg < DD)        base = x + (size_t)n * DD + kg;
                else if (kg < 2*DD) base = g_agg + (size_t)n * DD + (kg - DD);
                else                base = attr_or_f + (size_t)n * DD + (kg - 2*DD);
            }
            float4 v0 = *(const float4*)base;
            float4 v1 = *(const float4*)(base + 4);
            int kl = sub * 8;
            As[(kl+0)*TILE + e_l] = v0.x;
            As[(kl+1)*TILE + e_l] = v0.y;
            As[(kl+2)*TILE + e_l] = v0.z;
            As[(kl+3)*TILE + e_l] = v0.w;
            As[(kl+4)*TILE + e_l] = v1.x;
            As[(kl+5)*TILE + e_l] = v1.y;
            As[(kl+6)*TILE + e_l] = v1.z;
            As[(kl+7)*TILE + e_l] = v1.w;
        }
        // W1 tile (coalesced)
        {
            int krow = tid >> 5;
            int j4 = (tid & 31) << 2;
            *(float4*)&Bs[krow * HH + j4]       = *(const float4*)&W1[(size_t)(k0 + krow)     * HH + j4];
            *(float4*)&Bs[(krow + 8) * HH + j4] = *(const float4*)&W1[(size_t)(k0 + krow + 8) * HH + j4];
        }
        __syncthreads();
        #pragma unroll
        for (int kk = 0; kk < KB; kk++) {
            float4 a0  = *(float4*)&As[kk * TILE + row0];
            float4 a1  = *(float4*)&As[kk * TILE + row0 + 4];
            float4 b0  = *(float4*)&Bs[kk * HH + col0];
            float4 b1v = *(float4*)&Bs[kk * HH + col0 + 4];
            float a[8] = {a0.x, a0.y, a0.z, a0.w, a1.x, a1.y, a1.z, a1.w};
            float b[8] = {b0.x, b0.y, b0.z, b0.w, b1v.x, b1v.y, b1v.z, b1v.w};
            #pragma unroll
            for (int i = 0; i < 8; i++)
                #pragma unroll
                for (int j = 0; j < 8; j++)
                    acc[i][j] += a[i] * b[j];
        }
        __syncthreads();
    }

    // bias + relu -> Hs
    #pragma unroll
    for (int j = 0; j < 8; j++) {
        float bj = __ldg(&b1[col0 + j]);
        #pragma unroll
        for (int i = 0; i < 8; i++) {
            float v = acc[i][j] + bj;
            Hs[(row0 + i) * HS_LD + col0 + j] = fmaxf(v, 0.f);
        }
    }

    // ---------------- Stage 2: OUT = H @ W2 + b2, tile 128x64, K=128 --------
    const int rr0 = (tid >> 4) << 3;
    const int cc0 = (tid & 15) << 2;
    float acc2[8][4];
    #pragma unroll
    for (int i = 0; i < 8; i++)
        #pragma unroll
        for (int j = 0; j < 4; j++) acc2[i][j] = 0.f;

    #pragma unroll 1
    for (int k0 = 0; k0 < HH; k0 += KB) {
        __syncthreads();
        {
            int k = tid >> 4, j4 = (tid & 15) << 2;
            *(float4*)&B2s[k * DD + j4] = *(const float4*)&W2[(size_t)(k0 + k) * DD + j4];
        }
        __syncthreads();
        #pragma unroll
        for (int kk = 0; kk < KB; kk++) {
            float4 b = *(float4*)&B2s[kk * DD + cc0];
            #pragma unroll
            for (int i = 0; i < 8; i++) {
                float a = Hs[(rr0 + i) * HS_LD + k0 + kk];
                acc2[i][0] += a * b.x;
                acc2[i][1] += a * b.y;
                acc2[i][2] += a * b.z;
                acc2[i][3] += a * b.w;
            }
        }
    }

    float4 bb = *(const float4*)&b2[cc0];
    #pragma unroll
    for (int i = 0; i < 8; i++) {
        int r = r0 + rr0 + i;
        if (r < nrows) {
            float4 v;
            v.x = acc2[i][0] + bb.x;
            v.y = acc2[i][1] + bb.y;
            v.z = acc2[i][2] + bb.z;
            v.w = acc2[i][3] + bb.w;
            *(float4*)&out[(size_t)r * DD + cc0] = v;
            if (MODE == 0) {
                float* dst = &g_agg[(size_t)dst_s[rr0 + i] * DD + cc0];
                atomicAdd(dst + 0, v.x);
                atomicAdd(dst + 1, v.y);
                atomicAdd(dst + 2, v.z);
                atomicAdd(dst + 3, v.w);
            }
        }
    }
}

extern "C" void kernel_launch(void* const* d_in, const int* in_sizes, int n_in,
                              void* d_out, int out_size) {
    const float* x   = (const float*)d_in[0];
    const int*   ei  = (const int*)d_in[1];     // int32 indices
    const float* ea  = (const float*)d_in[2];
    const float* f   = (const float*)d_in[3];
    const float* We1 = (const float*)d_in[4];
    const float* be1 = (const float*)d_in[5];
    const float* We2 = (const float*)d_in[6];
    const float* be2 = (const float*)d_in[7];
    const float* Wn1 = (const float*)d_in[8];
    const float* bn1 = (const float*)d_in[9];
    const float* Wn2 = (const float*)d_in[10];
    const float* bn2 = (const float*)d_in[11];

    float* x_out    = (float*)d_out;                       // [N, D]
    float* edge_out = (float*)d_out + (size_t)NN * DD;     // [E, D]

    cudaFuncSetAttribute(mlp_fused_kernel<0>, cudaFuncAttributeMaxDynamicSharedMemorySize, SMEM_BYTES);
    cudaFuncSetAttribute(mlp_fused_kernel<1>, cudaFuncAttributeMaxDynamicSharedMemorySize, SMEM_BYTES);

    zero_agg_kernel<<<(NN * DD / 4 + 255) / 256, 256>>>();
    mlp_fused_kernel<0><<<EE / TILE, 256, SMEM_BYTES>>>(x, ei, ea, We1, be1, We2, be2, edge_out, EE);
    mlp_fused_kernel<1><<<(NN + TILE - 1) / TILE, 256, SMEM_BYTES>>>(x, ei, f, Wn1, bn1, Wn2, bn2, x_out, NN);
}

// round 5
// speedup vs baseline: 1.0399x; 1.0399x over previous
#include <cuda_runtime.h>

#define DD 64
#define HH 128
#define KK1 192
#define NN 20000
#define EE 640000
#define TILE 128
#define TILE2 (2*TILE)
#define KB 16
#define HS_LD 132

// Scratch for scatter-add aggregation (no device mallocs allowed).
__device__ __align__(16) float g_agg[NN * DD];

__global__ void zero_agg_kernel() {
    int i = blockIdx.x * blockDim.x + threadIdx.x;
    const int n4 = NN * DD / 4;
    if (i < n4) ((float4*)g_agg)[i] = make_float4(0.f, 0.f, 0.f, 0.f);
}

typedef unsigned long long ull;

__device__ __forceinline__ ull pack2(float lo, float hi) {
    ull r;
    asm("mov.b64 %0, {%1, %2};" : "=l"(r) : "f"(lo), "f"(hi));
    return r;
}
__device__ __forceinline__ void unpack2(ull v, float &lo, float &hi) {
    asm("mov.b64 {%0, %1}, %2;" : "=f"(lo), "=f"(hi) : "l"(v));
}
__device__ __forceinline__ void ffma2(ull &d, ull a, ull b) {
    asm("fma.rn.f32x2 %0, %1, %2, %0;" : "+l"(d) : "l"(a), "l"(b));
}

constexpr int SMEM_FLOATS = KB * TILE2 + KB * HH + TILE * HS_LD + KB * DD;
constexpr int SMEM_BYTES  = SMEM_FLOATS * 4 + 2 * TILE * 4;

// Fused 2-layer MLP over gathered rows, fp32x2 packed FMA (sm_103a FFMA2).
// MODE 0 (edge): A = [x[src] | x[dest] | edge_attr], out=edge_out, scatter-add to g_agg[dest]
// MODE 1 (node): A = [x | g_agg | f],                out=x_out
template <int MODE>
__global__ void __launch_bounds__(256, 2)
mlp_fused_kernel(const float* __restrict__ x,
                 const int* __restrict__ edge_index,   // int32 (JAX x64 disabled)
                 const float* __restrict__ attr_or_f,
                 const float* __restrict__ W1,
                 const float* __restrict__ b1,
                 const float* __restrict__ W2,
                 const float* __restrict__ b2,
                 float* __restrict__ out,
                 int nrows)
{
    extern __shared__ float smem[];
    float* As2 = smem;                  // [KB][TILE2]  duplicated pairs
    float* Bs  = As2 + KB * TILE2;      // [KB][HH]
    float* Hs  = Bs + KB * HH;          // [TILE][HS_LD]
    float* B2s = Hs + TILE * HS_LD;     // [KB][DD]
    int*  src_s = (int*)(B2s + KB * DD);
    int*  dst_s = src_s + TILE;

    const int tid = threadIdx.x;
    const int r0  = blockIdx.x * TILE;

    if (MODE == 0 && tid < TILE) {
        int e = r0 + tid;
        int s = edge_index[e];
        int d = edge_index[EE + e];
        src_s[tid] = (s < 0) ? 0 : (s >= NN ? NN - 1 : s);
        dst_s[tid] = (d < 0) ? 0 : (d >= NN ? NN - 1 : d);
    }
    __syncthreads();

    // ---------------- Stage 1: H = relu(A @ W1 + b1), tile 128x128, K=192 ----
    const int ty = tid >> 4, tx = tid & 15;
    const int row0 = ty << 3;
    const int ca = tx << 2;           // cols ca..ca+3
    const int cb = 64 + (tx << 2);    // cols cb..cb+3
    const int e_l = tid >> 1;
    const int sub = tid & 1;

    ull accp[8][4];
    #pragma unroll
    for (int i = 0; i < 8; i++)
        #pragma unroll
        for (int j = 0; j < 4; j++) accp[i][j] = 0ULL;

    #pragma unroll 1
    for (int k0 = 0; k0 < KK1; k0 += KB) {
        // Gather A tile: thread loads 8 consecutive k for one row, stores duplicated
        {
            int kg = k0 + sub * 8;
            const float* base;
            if (MODE == 0) {
                if (kg < DD)        base = x + (size_t)src_s[e_l] * DD + kg;
                else if (kg < 2*DD) base = x + (size_t)dst_s[e_l] * DD + (kg - DD);
                else                base = attr_or_f + (size_t)(r0 + e_l) * DD + (kg - 2*DD);
            } else {
                int n = r0 + e_l; if (n >= nrows) n = nrows - 1;
                if (kg < DD)        base = x + (size_t)n * DD + kg;
                else if (kg < 2*DD) base = g_agg + (size_t)n * DD + (kg - DD);
                else                base = attr_or_f + (size_t)n * DD + (kg - 2*DD);
            }
            float4 v0 = *(const float4*)base;
            float4 v1 = *(const float4*)(base + 4);
            int kl = sub * 8;
            int c2 = e_l << 1;
            *(float2*)&As2[(kl+0)*TILE2 + c2] = make_float2(v0.x, v0.x);
            *(float2*)&As2[(kl+1)*TILE2 + c2] = make_float2(v0.y, v0.y);
            *(float2*)&As2[(kl+2)*TILE2 + c2] = make_float2(v0.z, v0.z);
            *(float2*)&As2[(kl+3)*TILE2 + c2] = make_float2(v0.w, v0.w);
            *(float2*)&As2[(kl+4)*TILE2 + c2] = make_float2(v1.x, v1.x);
            *(float2*)&As2[(kl+5)*TILE2 + c2] = make_float2(v1.y, v1.y);
            *(float2*)&As2[(kl+6)*TILE2 + c2] = make_float2(v1.z, v1.z);
            *(float2*)&As2[(kl+7)*TILE2 + c2] = make_float2(v1.w, v1.w);
        }
        // W1 tile (coalesced)
        {
            int krow = tid >> 5;
            int j4 = (tid & 31) << 2;
            *(float4*)&Bs[krow * HH + j4]       = *(const float4*)&W1[(size_t)(k0 + krow)     * HH + j4];
            *(float4*)&Bs[(krow + 8) * HH + j4] = *(const float4*)&W1[(size_t)(k0 + krow + 8) * HH + j4];
        }
        __syncthreads();
        #pragma unroll
        for (int kk = 0; kk < KB; kk++) {
            // a broadcasts: duplicated pairs read directly as 64-bit lanes
            ulonglong2 A0 = *(const ulonglong2*)&As2[kk * TILE2 + (row0 << 1)];
            ulonglong2 A1 = *(const ulonglong2*)&As2[kk * TILE2 + (row0 << 1) + 4];
            ulonglong2 A2 = *(const ulonglong2*)&As2[kk * TILE2 + (row0 << 1) + 8];
            ulonglong2 A3 = *(const ulonglong2*)&As2[kk * TILE2 + (row0 << 1) + 12];
            // b pairs: natural 64-bit views of consecutive columns
            ulonglong2 B0 = *(const ulonglong2*)&Bs[kk * HH + ca];
            ulonglong2 B1 = *(const ulonglong2*)&Bs[kk * HH + cb];
            ull a[8] = {A0.x, A0.y, A1.x, A1.y, A2.x, A2.y, A3.x, A3.y};
            #pragma unroll
            for (int i = 0; i < 8; i++) {
                ffma2(accp[i][0], a[i], B0.x);
                ffma2(accp[i][1], a[i], B0.y);
                ffma2(accp[i][2], a[i], B1.x);
                ffma2(accp[i][3], a[i], B1.y);
            }
        }
        __syncthreads();
    }

    // bias + relu -> Hs (cols ca..ca+3 and cb..cb+3)
    {
        float4 ba = *(const float4*)&b1[ca];
        float4 bb = *(const float4*)&b1[cb];
        #pragma unroll
        for (int i = 0; i < 8; i++) {
            float c0, c1, c2, c3;
            unpack2(accp[i][0], c0, c1);
            unpack2(accp[i][1], c2, c3);
            float4 va = make_float4(fmaxf(c0 + ba.x, 0.f), fmaxf(c1 + ba.y, 0.f),
                                    fmaxf(c2 + ba.z, 0.f), fmaxf(c3 + ba.w, 0.f));
            *(float4*)&Hs[(row0 + i) * HS_LD + ca] = va;
            unpack2(accp[i][2], c0, c1);
            unpack2(accp[i][3], c2, c3);
            float4 vb = make_float4(fmaxf(c0 + bb.x, 0.f), fmaxf(c1 + bb.y, 0.f),
                                    fmaxf(c2 + bb.z, 0.f), fmaxf(c3 + bb.w, 0.f));
            *(float4*)&Hs[(row0 + i) * HS_LD + cb] = vb;
        }
    }

    // ---------------- Stage 2: OUT = H @ W2 + b2, tile 128x64, K=128 --------
    const int rr0 = (tid >> 4) << 3;
    const int cc0 = (tid & 15) << 2;
    ull acc2p[8][2];
    #pragma unroll
    for (int i = 0; i < 8; i++) { acc2p[i][0] = 0ULL; acc2p[i][1] = 0ULL; }

    #pragma unroll 1
    for (int k0 = 0; k0 < HH; k0 += KB) {
        __syncthreads();
        {
            int k = tid >> 4, j4 = (tid & 15) << 2;
            *(float4*)&B2s[k * DD + j4] = *(const float4*)&W2[(size_t)(k0 + k) * DD + j4];
        }
        __syncthreads();
        #pragma unroll
        for (int kk = 0; kk < KB; kk++) {
            ulonglong2 B = *(const ulonglong2*)&B2s[kk * DD + cc0];
            #pragma unroll
            for (int i = 0; i < 8; i++) {
                float av = Hs[(rr0 + i) * HS_LD + k0 + kk];
                ull ap = pack2(av, av);
                ffma2(acc2p[i][0], ap, B.x);
                ffma2(acc2p[i][1], ap, B.y);
            }
        }
    }

    float4 bb2 = *(const float4*)&b2[cc0];
    #pragma unroll
    for (int i = 0; i < 8; i++) {
        int r = r0 + rr0 + i;
        if (r < nrows) {
            float c0, c1, c2, c3;
            unpack2(acc2p[i][0], c0, c1);
            unpack2(acc2p[i][1], c2, c3);
            float4 v;
            v.x = c0 + bb2.x;
            v.y = c1 + bb2.y;
            v.z = c2 + bb2.z;
            v.w = c3 + bb2.w;
            *(float4*)&out[(size_t)r * DD + cc0] = v;
            if (MODE == 0) {
                float* dst = &g_agg[(size_t)dst_s[rr0 + i] * DD + cc0];
                atomicAdd(dst + 0, v.x);
                atomicAdd(dst + 1, v.y);
                atomicAdd(dst + 2, v.z);
                atomicAdd(dst + 3, v.w);
            }
        }
    }
}

extern "C" void kernel_launch(void* const* d_in, const int* in_sizes, int n_in,
                              void* d_out, int out_size) {
    const float* x   = (const float*)d_in[0];
    const int*   ei  = (const int*)d_in[1];     // int32 indices
    const float* ea  = (const float*)d_in[2];
    const float* f   = (const float*)d_in[3];
    const float* We1 = (const float*)d_in[4];
    const float* be1 = (const float*)d_in[5];
    const float* We2 = (const float*)d_in[6];
    const float* be2 = (const float*)d_in[7];
    const float* Wn1 = (const float*)d_in[8];
    const float* bn1 = (const float*)d_in[9];
    const float* Wn2 = (const float*)d_in[10];
    const float* bn2 = (const float*)d_in[11];

    float* x_out    = (float*)d_out;                       // [N, D]
    float* edge_out = (float*)d_out + (size_t)NN * DD;     // [E, D]

    cudaFuncSetAttribute(mlp_fused_kernel<0>, cudaFuncAttributeMaxDynamicSharedMemorySize, SMEM_BYTES);
    cudaFuncSetAttribute(mlp_fused_kernel<1>, cudaFuncAttributeMaxDynamicSharedMemorySize, SMEM_BYTES);

    zero_agg_kernel<<<(NN * DD / 4 + 255) / 256, 256>>>();
    mlp_fused_kernel<0><<<EE / TILE, 256, SMEM_BYTES>>>(x, ei, ea, We1, be1, We2, be2, edge_out, EE);
    mlp_fused_kernel<1><<<(NN + TILE - 1) / TILE, 256, SMEM_BYTES>>>(x, ei, f, Wn1, bn1, Wn2, bn2, x_out, NN);
}